// round 5
// baseline (speedup 1.0000x reference)
#include <cuda_runtime.h>
#include <cstdint>

// Problem constants (fixed by the reference: B=262144, NUM_CLASSES=1000)
#define NROWS       262144
#define NCLASSES    1000
#define ROW_STRIDE  1004          // 4 box + 1000 logits, row = 4016 bytes (16B aligned)
#define NVEC4       250           // 1000 logits / 4 per float4
#define WARPS_PER_BLOCK 8
#define BLOCK_THREADS   (WARPS_PER_BLOCK * 32)

__device__ double g_acc;

__global__ void zero_acc_kernel() { g_acc = 0.0; }

__global__ __launch_bounds__(BLOCK_THREADS)
void loss_kernel(const float* __restrict__ out, const float* __restrict__ tgt)
{
    const int lane   = threadIdx.x & 31;
    const int warpid = threadIdx.x >> 5;
    const int row    = blockIdx.x * WARPS_PER_BLOCK + warpid;   // one row per warp

    const float* rowp = out + (size_t)row * ROW_STRIDE;
    // logits start at +4 floats = +16 bytes -> still 16B aligned
    const float4* logits4 = (const float4*)(rowp + 4);

    // ---- single memory pass: load up to 8 float4 per lane into registers ----
    float v[32];
    float m = -1e30f;
    #pragma unroll
    for (int j = 0; j < 8; ++j) {
        const int idx = j * 32 + lane;               // 0..255, valid < 250
        float4 q;
        if (idx < NVEC4) {
            q = logits4[idx];
        } else {
            q = make_float4(-1e30f, -1e30f, -1e30f, -1e30f);
        }
        v[4*j+0] = q.x; v[4*j+1] = q.y; v[4*j+2] = q.z; v[4*j+3] = q.w;
        m = fmaxf(m, fmaxf(fmaxf(q.x, q.y), fmaxf(q.z, q.w)));
    }

    // warp max reduction
    #pragma unroll
    for (int o = 16; o > 0; o >>= 1)
        m = fmaxf(m, __shfl_xor_sync(0xFFFFFFFFu, m, o));

    // register pass 2: sum of exp(x - m)  (pads contribute exp(-huge) = 0)
    float s = 0.0f;
    #pragma unroll
    for (int k = 0; k < 32; ++k)
        s += __expf(v[k] - m);

    #pragma unroll
    for (int o = 16; o > 0; o >>= 1)
        s += __shfl_xor_sync(0xFFFFFFFFu, s, o);

    __shared__ float partial[WARPS_PER_BLOCK];

    if (lane == 0) {
        const float lse = m + __logf(s);             // logsumexp(logits)

        // target row: 5 floats (not 16B aligned -> scalar loads)
        const float* t = tgt + (size_t)row * 5;
        const float xmin = t[0], ymin = t[1], xmax = t[2], ymax = t[3];
        const int   cid  = (int)t[4];

        // box prediction: first 4 floats of the row (16B aligned)
        const float4 bp = *(const float4*)rowp;

        const float cx = (xmin + xmax) * 0.5f;
        const float cy = (ymin + ymax) * 0.5f;
        const float bw = xmax - xmin;
        const float bh = ymax - ymin;

        const float d0 = bp.x - cx, d1 = bp.y - cy, d2 = bp.z - bw, d3 = bp.w - bh;
        const float loc_loss = 0.25f * (d0*d0 + d1*d1 + d2*d2 + d3*d3);

        // target-class logit: one extra LDG, L1-hot (this warp just streamed the row)
        const float cls_loss = lse - rowp[4 + cid];

        partial[warpid] = loc_loss + cls_loss;
    }
    __syncthreads();

    if (threadIdx.x == 0) {
        float blk = 0.0f;
        #pragma unroll
        for (int i = 0; i < WARPS_PER_BLOCK; ++i) blk += partial[i];
        atomicAdd(&g_acc, (double)blk);
    }
}

__global__ void finalize_kernel(float* __restrict__ dst)
{
    dst[0] = (float)(g_acc / (double)NROWS);
}

extern "C" void kernel_launch(void* const* d_in, const int* in_sizes, int n_in,
                              void* d_out, int out_size)
{
    const float* out_t = (const float*)d_in[0];   // (B, 1004) float32
    const float* tgt_t = (const float*)d_in[1];   // (B, 5)    float32
    float* dst = (float*)d_out;

    zero_acc_kernel<<<1, 1>>>();
    loss_kernel<<<NROWS / WARPS_PER_BLOCK, BLOCK_THREADS>>>(out_t, tgt_t);
    finalize_kernel<<<1, 1>>>(dst);
}